// round 14
// baseline (speedup 1.0000x reference)
#include <cuda_runtime.h>
#include <cuda_fp16.h>

#define NUx 200000
#define NIx 100000
#define Dx  64
#define Ex  2000000
#define Bx  8192
#define EPSx 1e-12f

#define SB 256
#define SI 8                 // 2048 elements per scan block
#define NW (SB/32)

#define FILLB ((Ex + 255) / 256)                    // fill part of cvtfill
#define CVTB  (((NUx + NIx) * 8 + 255) / 256)       // cvt part: 2 float4/thread
#define DEGB  ((Ex / 4 + 255) / 256)                // 4 edges per thread
#define SCANB_U ((NUx + SB * SI - 1) / (SB * SI))   // 98
#define SCANB_I ((NIx + SB * SI - 1) / (SB * SI))   // 49

// ---- static device scratch (no allocation allowed) ----
// g_deg is zero at kernel_launch entry: static-init zero on first run,
// re-zeroed by k_out at the end of every run.
__device__ int g_deg[NUx + NIx];     // users [0,NU), items [NU,NU+NI)
__device__ float g_rsd[NUx + NIx];   // rsqrt(max(deg,1))
__device__ int g_off_u[NUx];
__device__ int g_off_i[NIx];
__device__ int g_cur_u[NUx];
__device__ int g_cur_i[NIx];
__device__ int g_bsum_u[128];
__device__ int g_bsum_i[128];
__device__ int g_adj_u[Ex];          // per-user neighbor items (ids only)
__device__ int g_adj_i[Ex];          // per-item neighbor users (ids only)

// fp16 PRE-SCALED feature storage (rows of 32 half2 = 128B):
// stored value = rsd[node] * feature (the gather-side weight is baked in).
__device__ __align__(256) __half2 g_uf16[(size_t)NUx * 32];
__device__ __align__(256) __half2 g_if16[(size_t)NIx * 32];
__device__ __align__(256) __half2 g_hu16[3][(size_t)NUx * 32];
__device__ __align__(256) __half2 g_hi16[3][(size_t)NIx * 32];

// ---- degree histogram (4 edges per thread) ----
__global__ void k_deg(const int* __restrict__ eu, const int* __restrict__ ei) {
    int e4 = blockIdx.x * blockDim.x + threadIdx.x;
    if (e4 < Ex / 4) {
        int4 u4 = ((const int4*)eu)[e4];
        int4 i4 = ((const int4*)ei)[e4];
        atomicAdd(&g_deg[u4.x], 1);
        atomicAdd(&g_deg[u4.y], 1);
        atomicAdd(&g_deg[u4.z], 1);
        atomicAdd(&g_deg[u4.w], 1);
        atomicAdd(&g_deg[NUx + i4.x], 1);
        atomicAdd(&g_deg[NUx + i4.y], 1);
        atomicAdd(&g_deg[NUx + i4.z], 1);
        atomicAdd(&g_deg[NUx + i4.w], 1);
    }
}

// ---- exclusive scan stage 1 for BOTH segments in one launch ----
__global__ void k_scan_blocks2() {
    const int* in; int* out; int* bsum; int n; int blk;
    if (blockIdx.x < SCANB_U) {
        in = g_deg; out = g_off_u; bsum = g_bsum_u; n = NUx; blk = blockIdx.x;
    } else {
        in = g_deg + NUx; out = g_off_i; bsum = g_bsum_i; n = NIx; blk = blockIdx.x - SCANB_U;
    }
    __shared__ int warp_tot[NW];
    int lane = threadIdx.x & 31, wid = threadIdx.x >> 5;
    int base = blk * (SB * SI) + threadIdx.x * SI;

    int v[SI];
    int s = 0;
    #pragma unroll
    for (int k = 0; k < SI; ++k) {
        int idx = base + k;
        v[k] = (idx < n) ? in[idx] : 0;
        s += v[k];
    }
    int ps = s;
    #pragma unroll
    for (int o = 1; o < 32; o <<= 1) {
        int t = __shfl_up_sync(0xffffffffu, ps, o);
        if (lane >= o) ps += t;
    }
    if (lane == 31) warp_tot[wid] = ps;
    __syncthreads();
    if (wid == 0) {
        int wt = (lane < NW) ? warp_tot[lane] : 0;
        int wps = wt;
        #pragma unroll
        for (int o = 1; o < NW; o <<= 1) {
            int t = __shfl_up_sync(0xffffffffu, wps, o);
            if (lane >= o) wps += t;
        }
        if (lane < NW) warp_tot[lane] = wps - wt;
    }
    __syncthreads();
    int excl = warp_tot[wid] + (ps - s);
    int run = excl;
    #pragma unroll
    for (int k = 0; k < SI; ++k) {
        int idx = base + k;
        if (idx < n) out[idx] = run;
        run += v[k];
    }
    if (threadIdx.x == SB - 1) bsum[blk] = excl + s;
}

// ---- scan stage 2+3 fused: each block self-computes its bsum prefix ----
__global__ void k_scan_add2() {
    int* out; int* cur; const int* bsum; int n; int blk;
    if (blockIdx.x < SCANB_U) {
        out = g_off_u; cur = g_cur_u; bsum = g_bsum_u; n = NUx; blk = blockIdx.x;
    } else {
        out = g_off_i; cur = g_cur_i; bsum = g_bsum_i; n = NIx; blk = blockIdx.x - SCANB_U;
    }
    __shared__ int ssum[NW];
    int part = 0;
    for (int k = threadIdx.x; k < blk; k += SB) part += bsum[k];
    #pragma unroll
    for (int o = 16; o; o >>= 1) part += __shfl_xor_sync(0xffffffffu, part, o);
    if ((threadIdx.x & 31) == 0) ssum[threadIdx.x >> 5] = part;
    __syncthreads();
    int add = 0;
    #pragma unroll
    for (int k = 0; k < NW; ++k) add += ssum[k];

    int base = blk * (SB * SI) + threadIdx.x * SI;
    #pragma unroll
    for (int k = 0; k < SI; ++k) {
        int idx = base + k;
        if (idx < n) {
            int val = out[idx] + add;
            out[idx] = val;
            cur[idx] = val;
        }
    }
}

// ---- fused: id-only counting-sort fill + rsd-scaled fp16 convert ----
// fill blocks first (long pole), cvt blocks after; both dependencies ready
// (fill needs offsets, cvt needs deg); they run concurrently in one launch.
__global__ void k_cvtfill(const float* __restrict__ uf, const float* __restrict__ itf,
                          const int* __restrict__ eu, const int* __restrict__ ei) {
    if (blockIdx.x < FILLB) {
        int e = blockIdx.x * blockDim.x + threadIdx.x;
        if (e < Ex) {
            int u = eu[e], i = ei[e];
            int pu = atomicAdd(&g_cur_u[u], 1);
            g_adj_u[pu] = i;
            int pi = atomicAdd(&g_cur_i[i], 1);
            g_adj_i[pi] = u;
        }
    } else {
        // one thread = 2 float4 in, 1 uint4 (4 half2) out
        int t = (blockIdx.x - FILLB) * blockDim.x + threadIdx.x;
        if (t < NUx * 8) {
            int row = t >> 3;
            float rsd = rsqrtf((float)max(g_deg[row], 1));
            if ((t & 7) == 0) g_rsd[row] = rsd;
            float4 fa = ((const float4*)uf)[t * 2];
            float4 fb = ((const float4*)uf)[t * 2 + 1];
            __half2 h0 = __float22half2_rn(make_float2(fa.x * rsd, fa.y * rsd));
            __half2 h1 = __float22half2_rn(make_float2(fa.z * rsd, fa.w * rsd));
            __half2 h2 = __float22half2_rn(make_float2(fb.x * rsd, fb.y * rsd));
            __half2 h3 = __float22half2_rn(make_float2(fb.z * rsd, fb.w * rsd));
            ((uint4*)g_uf16)[t] = make_uint4(*(unsigned*)&h0, *(unsigned*)&h1,
                                             *(unsigned*)&h2, *(unsigned*)&h3);
        } else if (t < (NUx + NIx) * 8) {
            int s = t - NUx * 8;
            int row = s >> 3;
            float rsd = rsqrtf((float)max(g_deg[NUx + row], 1));
            if ((s & 7) == 0) g_rsd[NUx + row] = rsd;
            float4 fa = ((const float4*)itf)[s * 2];
            float4 fb = ((const float4*)itf)[s * 2 + 1];
            __half2 h0 = __float22half2_rn(make_float2(fa.x * rsd, fa.y * rsd));
            __half2 h1 = __float22half2_rn(make_float2(fa.z * rsd, fa.w * rsd));
            __half2 h2 = __float22half2_rn(make_float2(fb.x * rsd, fb.y * rsd));
            __half2 h3 = __float22half2_rn(make_float2(fb.z * rsd, fb.w * rsd));
            ((uint4*)g_if16)[s] = make_uint4(*(unsigned*)&h0, *(unsigned*)&h1,
                                             *(unsigned*)&h2, *(unsigned*)&h3);
        }
    }
}

// ---- merged both-direction gather-aggregate + fused L2-normalize ----
// ONE WARP PER TWO CONSECUTIVE DEST ROWS. Adjacency batch held in a register
// per lane and broadcast via __shfl_sync (no smem, no syncwarp in hot loop).
// Sources pre-scaled by rsd_src; epilogue multiplies by rsd_dest so output is
// pre-scaled for the next layer.
__global__ void k_agg(const __half2* __restrict__ srcU,
                      const __half2* __restrict__ srcI,
                      __half2* __restrict__ houtU,
                      __half2* __restrict__ houtI) {
    int gw = (blockIdx.x * blockDim.x + threadIdx.x) >> 5;   // pair index
    int lane = threadIdx.x & 31;
    const int PI = NIx / 2, PU = NUx / 2;
    if (gw >= PI + PU) return;

    const __half2* src;
    __half2* hout;
    const int* adj;
    const int* off;
    const float* rsd;
    int row0, nrows;
    if (gw < PI) {
        row0 = gw * 2; nrows = NIx;
        src = srcU; hout = houtI; adj = g_adj_i; off = g_off_i; rsd = g_rsd + NUx;
    } else {
        row0 = (gw - PI) * 2; nrows = NUx;
        src = srcI; hout = houtU; adj = g_adj_u; off = g_off_u; rsd = g_rsd;
    }

    int beg = off[row0];
    int mid = off[row0 + 1];
    int end = (row0 + 2 < nrows) ? off[row0 + 2] : Ex;

    float2 acc0 = make_float2(0.f, 0.f);
    float2 acc1 = make_float2(0.f, 0.f);

    for (int p = beg; p < end; p += 32) {
        int idx = p + lane;
        int a = (idx < end) ? adj[idx] : 0;
        int c = min(end - p, 32);
        #pragma unroll 4
        for (int j = 0; j < c; ++j) {
            int id = __shfl_sync(0xffffffffu, a, j);
            float2 v = __half22float2(src[(size_t)id * 32 + lane]);
            if (p + j < mid) {                 // warp-uniform branch
                acc0.x += v.x; acc0.y += v.y;
            } else {
                acc1.x += v.x; acc1.y += v.y;
            }
        }
    }

    float s0 = acc0.x * acc0.x + acc0.y * acc0.y;
    float s1 = acc1.x * acc1.x + acc1.y * acc1.y;
    #pragma unroll
    for (int o = 16; o; o >>= 1) {
        s0 += __shfl_xor_sync(0xffffffffu, s0, o);
        s1 += __shfl_xor_sync(0xffffffffu, s1, o);
    }
    float inv0 = rsd[row0]     / fmaxf(sqrtf(s0), EPSx);
    float inv1 = rsd[row0 + 1] / fmaxf(sqrtf(s1), EPSx);

    hout[(size_t)row0 * 32 + lane] =
        __float22half2_rn(make_float2(acc0.x * inv0, acc0.y * inv0));
    hout[(size_t)(row0 + 1) * 32 + lane] =
        __float22half2_rn(make_float2(acc1.x * inv1, acc1.y * inv1));
}

// ---- final gather: e = f + (h0 + h1/2 + h2/3)/rsd_dest;  deg re-zero ----
__global__ void k_out(const float* __restrict__ uf, const float* __restrict__ itf,
                      const int* __restrict__ users, const int* __restrict__ pos,
                      const int* __restrict__ neg, float* __restrict__ out) {
    unsigned t = blockIdx.x * blockDim.x + threadIdx.x;
    if (t < NUx + NIx) g_deg[t] = 0;    // restore invariant for next replay
    unsigned r = t >> 4;
    unsigned lane = t & 15u;            // 16 lanes x 4 cols = 64
    if (r >= 3u * Bx) return;
    unsigned grp = r / Bx, idx = r % Bx;

    const float* base;
    const __half2 *h0, *h1, *h2;
    float rsd;
    size_t row;
    if (grp == 0) {
        row = (size_t)users[idx];
        base = uf + row * Dx;
        rsd = g_rsd[row];
        h0 = g_hu16[0] + row * 32; h1 = g_hu16[1] + row * 32; h2 = g_hu16[2] + row * 32;
    } else {
        row = (size_t)((grp == 1) ? pos[idx] : neg[idx]);
        base = itf + row * Dx;
        rsd = g_rsd[NUx + row];
        h0 = g_hi16[0] + row * 32; h1 = g_hi16[1] + row * 32; h2 = g_hi16[2] + row * 32;
    }
    float un = 1.0f / rsd;   // unscale stored h' back to l2-normalized h

    float4 f = *(const float4*)(base + lane * 4);
    float2 a0 = __half22float2(h0[lane * 2]), b0 = __half22float2(h0[lane * 2 + 1]);
    float2 a1 = __half22float2(h1[lane * 2]), b1 = __half22float2(h1[lane * 2 + 1]);
    float2 a2 = __half22float2(h2[lane * 2]), b2 = __half22float2(h2[lane * 2 + 1]);

    const float c1 = 0.5f, c2 = 1.0f / 3.0f;
    f.x += (a0.x + c1 * a1.x + c2 * a2.x) * un;
    f.y += (a0.y + c1 * a1.y + c2 * a2.y) * un;
    f.z += (b0.x + c1 * b1.x + c2 * b2.x) * un;
    f.w += (b0.y + c1 * b1.y + c2 * b2.y) * un;

    *(float4*)(out + (size_t)r * Dx + lane * 4) = f;
}

extern "C" void kernel_launch(void* const* d_in, const int* in_sizes, int n_in,
                              void* d_out, int out_size) {
    const float* uf  = (const float*)d_in[0];
    const float* itf = (const float*)d_in[1];
    const int*   eu  = (const int*)d_in[2];
    const int*   ei  = (const int*)d_in[3];
    const int*   usr = (const int*)d_in[4];
    const int*   pos = (const int*)d_in[5];
    const int*   neg = (const int*)d_in[6];
    float* out = (float*)d_out;

    void *p_uf16, *p_if16, *p_hu[3], *p_hi[3];
    cudaGetSymbolAddress(&p_uf16, g_uf16);
    cudaGetSymbolAddress(&p_if16, g_if16);
    {
        void* tmp;
        cudaGetSymbolAddress(&tmp, g_hu16);
        for (int k = 0; k < 3; ++k) p_hu[k] = (char*)tmp + (size_t)k * NUx * 32 * sizeof(__half2);
        cudaGetSymbolAddress(&tmp, g_hi16);
        for (int k = 0; k < 3; ++k) p_hi[k] = (char*)tmp + (size_t)k * NIx * 32 * sizeof(__half2);
    }

    // ---- CSR build + pre-scaled fp16 staging (4 launches before agg) ----
    // g_deg is zero at entry (static init on run 1; k_out re-zeroes it)
    k_deg<<<DEGB, 256>>>(eu, ei);                                    // #1
    k_scan_blocks2<<<SCANB_U + SCANB_I, SB>>>();                     // #2
    k_scan_add2<<<SCANB_U + SCANB_I, SB>>>();                        // #3
    k_cvtfill<<<FILLB + CVTB, 256>>>(uf, itf, eu, ei);               // #4

    const unsigned npairs = (NUx + NIx) / 2;
    const unsigned gagg = (unsigned)(((size_t)npairs * 32 + 255) / 256);

    // ---- 3 propagation layers ----
    k_agg<<<gagg, 256>>>((const __half2*)p_uf16, (const __half2*)p_if16,
                         (__half2*)p_hu[0], (__half2*)p_hi[0]);
    k_agg<<<gagg, 256>>>((const __half2*)p_hu[0], (const __half2*)p_hi[0],
                         (__half2*)p_hu[1], (__half2*)p_hi[1]);
    k_agg<<<gagg, 256>>>((const __half2*)p_hu[1], (const __half2*)p_hi[1],
                         (__half2*)p_hu[2], (__half2*)p_hi[2]);

    // ---- output gather (unscale h', compute e on the fly) ----
    k_out<<<(3 * Bx * 16 + 255) / 256, 256>>>(uf, itf, usr, pos, neg, out);
}

// round 15
// speedup vs baseline: 1.2121x; 1.2121x over previous
#include <cuda_runtime.h>
#include <cuda_fp16.h>

#define NUx 200000
#define NIx 100000
#define Dx  64
#define Ex  2000000
#define Bx  8192
#define EPSx 1e-12f

#define SB 256
#define SI 8                 // 2048 elements per scan block
#define NW (SB/32)

#define FILLB ((Ex + 255) / 256)                    // fill part of cvtfill
#define CVTB  (((NUx + NIx) * 8 + 255) / 256)       // cvt part: 2 float4/thread
#define DEGB  ((Ex / 4 + 255) / 256)                // 4 edges per thread
#define SCANB_U ((NUx + SB * SI - 1) / (SB * SI))   // 98
#define SCANB_I ((NIx + SB * SI - 1) / (SB * SI))   // 49

// ---- static device scratch (no allocation allowed) ----
// g_deg is zero at kernel_launch entry: static-init zero on first run,
// re-zeroed by k_out at the end of every run.
__device__ int g_deg[NUx + NIx];     // users [0,NU), items [NU,NU+NI)
__device__ float g_rsd[NUx + NIx];   // rsqrt(max(deg,1))
__device__ int g_off_u[NUx];
__device__ int g_off_i[NIx];
__device__ int g_cur_u[NUx];
__device__ int g_cur_i[NIx];
__device__ int g_bsum_u[128];
__device__ int g_bsum_i[128];
__device__ int g_adj_u[Ex];          // per-user neighbor items (ids only)
__device__ int g_adj_i[Ex];          // per-item neighbor users (ids only)

// fp16 PRE-SCALED feature storage (rows of 32 half2 = 128B):
// stored value = rsd[node] * feature (the gather-side weight is baked in).
__device__ __align__(256) __half2 g_uf16[(size_t)NUx * 32];
__device__ __align__(256) __half2 g_if16[(size_t)NIx * 32];
__device__ __align__(256) __half2 g_hu16[3][(size_t)NUx * 32];
__device__ __align__(256) __half2 g_hi16[3][(size_t)NIx * 32];

// ---- degree histogram (4 edges per thread) ----
__global__ void k_deg(const int* __restrict__ eu, const int* __restrict__ ei) {
    int e4 = blockIdx.x * blockDim.x + threadIdx.x;
    if (e4 < Ex / 4) {
        int4 u4 = ((const int4*)eu)[e4];
        int4 i4 = ((const int4*)ei)[e4];
        atomicAdd(&g_deg[u4.x], 1);
        atomicAdd(&g_deg[u4.y], 1);
        atomicAdd(&g_deg[u4.z], 1);
        atomicAdd(&g_deg[u4.w], 1);
        atomicAdd(&g_deg[NUx + i4.x], 1);
        atomicAdd(&g_deg[NUx + i4.y], 1);
        atomicAdd(&g_deg[NUx + i4.z], 1);
        atomicAdd(&g_deg[NUx + i4.w], 1);
    }
}

// ---- exclusive scan stage 1 for BOTH segments in one launch ----
__global__ void k_scan_blocks2() {
    const int* in; int* out; int* bsum; int n; int blk;
    if (blockIdx.x < SCANB_U) {
        in = g_deg; out = g_off_u; bsum = g_bsum_u; n = NUx; blk = blockIdx.x;
    } else {
        in = g_deg + NUx; out = g_off_i; bsum = g_bsum_i; n = NIx; blk = blockIdx.x - SCANB_U;
    }
    __shared__ int warp_tot[NW];
    int lane = threadIdx.x & 31, wid = threadIdx.x >> 5;
    int base = blk * (SB * SI) + threadIdx.x * SI;

    int v[SI];
    int s = 0;
    #pragma unroll
    for (int k = 0; k < SI; ++k) {
        int idx = base + k;
        v[k] = (idx < n) ? in[idx] : 0;
        s += v[k];
    }
    int ps = s;
    #pragma unroll
    for (int o = 1; o < 32; o <<= 1) {
        int t = __shfl_up_sync(0xffffffffu, ps, o);
        if (lane >= o) ps += t;
    }
    if (lane == 31) warp_tot[wid] = ps;
    __syncthreads();
    if (wid == 0) {
        int wt = (lane < NW) ? warp_tot[lane] : 0;
        int wps = wt;
        #pragma unroll
        for (int o = 1; o < NW; o <<= 1) {
            int t = __shfl_up_sync(0xffffffffu, wps, o);
            if (lane >= o) wps += t;
        }
        if (lane < NW) warp_tot[lane] = wps - wt;
    }
    __syncthreads();
    int excl = warp_tot[wid] + (ps - s);
    int run = excl;
    #pragma unroll
    for (int k = 0; k < SI; ++k) {
        int idx = base + k;
        if (idx < n) out[idx] = run;
        run += v[k];
    }
    if (threadIdx.x == SB - 1) bsum[blk] = excl + s;
}

// ---- scan stage 2+3 fused: each block self-computes its bsum prefix ----
__global__ void k_scan_add2() {
    int* out; int* cur; const int* bsum; int n; int blk;
    if (blockIdx.x < SCANB_U) {
        out = g_off_u; cur = g_cur_u; bsum = g_bsum_u; n = NUx; blk = blockIdx.x;
    } else {
        out = g_off_i; cur = g_cur_i; bsum = g_bsum_i; n = NIx; blk = blockIdx.x - SCANB_U;
    }
    __shared__ int ssum[NW];
    int part = 0;
    for (int k = threadIdx.x; k < blk; k += SB) part += bsum[k];
    #pragma unroll
    for (int o = 16; o; o >>= 1) part += __shfl_xor_sync(0xffffffffu, part, o);
    if ((threadIdx.x & 31) == 0) ssum[threadIdx.x >> 5] = part;
    __syncthreads();
    int add = 0;
    #pragma unroll
    for (int k = 0; k < NW; ++k) add += ssum[k];

    int base = blk * (SB * SI) + threadIdx.x * SI;
    #pragma unroll
    for (int k = 0; k < SI; ++k) {
        int idx = base + k;
        if (idx < n) {
            int val = out[idx] + add;
            out[idx] = val;
            cur[idx] = val;
        }
    }
}

// ---- fused: id-only counting-sort fill + rsd-scaled fp16 convert ----
// fill blocks first (long pole), cvt blocks after; both dependencies ready
// (fill needs offsets, cvt needs deg); they run concurrently in one launch.
__global__ void k_cvtfill(const float* __restrict__ uf, const float* __restrict__ itf,
                          const int* __restrict__ eu, const int* __restrict__ ei) {
    if (blockIdx.x < FILLB) {
        int e = blockIdx.x * blockDim.x + threadIdx.x;
        if (e < Ex) {
            int u = eu[e], i = ei[e];
            int pu = atomicAdd(&g_cur_u[u], 1);
            g_adj_u[pu] = i;
            int pi = atomicAdd(&g_cur_i[i], 1);
            g_adj_i[pi] = u;
        }
    } else {
        // one thread = 2 float4 in, 1 uint4 (4 half2) out
        int t = (blockIdx.x - FILLB) * blockDim.x + threadIdx.x;
        if (t < NUx * 8) {
            int row = t >> 3;
            float rsd = rsqrtf((float)max(g_deg[row], 1));
            if ((t & 7) == 0) g_rsd[row] = rsd;
            float4 fa = ((const float4*)uf)[t * 2];
            float4 fb = ((const float4*)uf)[t * 2 + 1];
            __half2 h0 = __float22half2_rn(make_float2(fa.x * rsd, fa.y * rsd));
            __half2 h1 = __float22half2_rn(make_float2(fa.z * rsd, fa.w * rsd));
            __half2 h2 = __float22half2_rn(make_float2(fb.x * rsd, fb.y * rsd));
            __half2 h3 = __float22half2_rn(make_float2(fb.z * rsd, fb.w * rsd));
            ((uint4*)g_uf16)[t] = make_uint4(*(unsigned*)&h0, *(unsigned*)&h1,
                                             *(unsigned*)&h2, *(unsigned*)&h3);
        } else if (t < (NUx + NIx) * 8) {
            int s = t - NUx * 8;
            int row = s >> 3;
            float rsd = rsqrtf((float)max(g_deg[NUx + row], 1));
            if ((s & 7) == 0) g_rsd[NUx + row] = rsd;
            float4 fa = ((const float4*)itf)[s * 2];
            float4 fb = ((const float4*)itf)[s * 2 + 1];
            __half2 h0 = __float22half2_rn(make_float2(fa.x * rsd, fa.y * rsd));
            __half2 h1 = __float22half2_rn(make_float2(fa.z * rsd, fa.w * rsd));
            __half2 h2 = __float22half2_rn(make_float2(fb.x * rsd, fb.y * rsd));
            __half2 h3 = __float22half2_rn(make_float2(fb.z * rsd, fb.w * rsd));
            ((uint4*)g_if16)[s] = make_uint4(*(unsigned*)&h0, *(unsigned*)&h1,
                                             *(unsigned*)&h2, *(unsigned*)&h3);
        }
    }
}

// ---- merged both-direction gather-aggregate + fused L2-normalize ----
// ONE WARP PER TWO CONSECUTIVE DEST ROWS, smem-staged adjacency (the proven
// R13 shape). Sources pre-scaled by rsd_src; epilogue multiplies by rsd_dest
// so output is pre-scaled for the next layer's gather.
__global__ void k_agg(const __half2* __restrict__ srcU,
                      const __half2* __restrict__ srcI,
                      __half2* __restrict__ houtU,
                      __half2* __restrict__ houtI) {
    __shared__ int sh[NW][32];
    int gw = (blockIdx.x * blockDim.x + threadIdx.x) >> 5;   // pair index
    int lane = threadIdx.x & 31;
    int wid = threadIdx.x >> 5;
    const int PI = NIx / 2, PU = NUx / 2;
    if (gw >= PI + PU) return;

    const __half2* src;
    __half2* hout;
    const int* adj;
    const int* off;
    const float* rsd;
    int row0, nrows;
    if (gw < PI) {
        row0 = gw * 2; nrows = NIx;
        src = srcU; hout = houtI; adj = g_adj_i; off = g_off_i; rsd = g_rsd + NUx;
    } else {
        row0 = (gw - PI) * 2; nrows = NUx;
        src = srcI; hout = houtU; adj = g_adj_u; off = g_off_u; rsd = g_rsd;
    }

    int beg = off[row0];
    int mid = off[row0 + 1];
    int end = (row0 + 2 < nrows) ? off[row0 + 2] : Ex;

    float2 acc0 = make_float2(0.f, 0.f);
    float2 acc1 = make_float2(0.f, 0.f);

    for (int p = beg; p < end; p += 32) {
        int idx = p + lane;
        if (idx < end) sh[wid][lane] = adj[idx];
        __syncwarp();
        int c = min(end - p, 32);
        #pragma unroll 4
        for (int j = 0; j < c; ++j) {
            int id = sh[wid][j];
            float2 v = __half22float2(src[(size_t)id * 32 + lane]);
            if (p + j < mid) {                 // warp-uniform branch
                acc0.x += v.x; acc0.y += v.y;
            } else {
                acc1.x += v.x; acc1.y += v.y;
            }
        }
        __syncwarp();
    }

    float s0 = acc0.x * acc0.x + acc0.y * acc0.y;
    float s1 = acc1.x * acc1.x + acc1.y * acc1.y;
    #pragma unroll
    for (int o = 16; o; o >>= 1) {
        s0 += __shfl_xor_sync(0xffffffffu, s0, o);
        s1 += __shfl_xor_sync(0xffffffffu, s1, o);
    }
    float inv0 = rsd[row0]     / fmaxf(sqrtf(s0), EPSx);
    float inv1 = rsd[row0 + 1] / fmaxf(sqrtf(s1), EPSx);

    hout[(size_t)row0 * 32 + lane] =
        __float22half2_rn(make_float2(acc0.x * inv0, acc0.y * inv0));
    hout[(size_t)(row0 + 1) * 32 + lane] =
        __float22half2_rn(make_float2(acc1.x * inv1, acc1.y * inv1));
}

// ---- final gather: e = f + (h0 + h1/2 + h2/3)/rsd_dest;  deg re-zero ----
__global__ void k_out(const float* __restrict__ uf, const float* __restrict__ itf,
                      const int* __restrict__ users, const int* __restrict__ pos,
                      const int* __restrict__ neg, float* __restrict__ out) {
    unsigned t = blockIdx.x * blockDim.x + threadIdx.x;
    if (t < NUx + NIx) g_deg[t] = 0;    // restore invariant for next replay
    unsigned r = t >> 4;
    unsigned lane = t & 15u;            // 16 lanes x 4 cols = 64
    if (r >= 3u * Bx) return;
    unsigned grp = r / Bx, idx = r % Bx;

    const float* base;
    const __half2 *h0, *h1, *h2;
    float rsd;
    size_t row;
    if (grp == 0) {
        row = (size_t)users[idx];
        base = uf + row * Dx;
        rsd = g_rsd[row];
        h0 = g_hu16[0] + row * 32; h1 = g_hu16[1] + row * 32; h2 = g_hu16[2] + row * 32;
    } else {
        row = (size_t)((grp == 1) ? pos[idx] : neg[idx]);
        base = itf + row * Dx;
        rsd = g_rsd[NUx + row];
        h0 = g_hi16[0] + row * 32; h1 = g_hi16[1] + row * 32; h2 = g_hi16[2] + row * 32;
    }
    float un = 1.0f / rsd;   // unscale stored h' back to l2-normalized h

    float4 f = *(const float4*)(base + lane * 4);
    float2 a0 = __half22float2(h0[lane * 2]), b0 = __half22float2(h0[lane * 2 + 1]);
    float2 a1 = __half22float2(h1[lane * 2]), b1 = __half22float2(h1[lane * 2 + 1]);
    float2 a2 = __half22float2(h2[lane * 2]), b2 = __half22float2(h2[lane * 2 + 1]);

    const float c1 = 0.5f, c2 = 1.0f / 3.0f;
    f.x += (a0.x + c1 * a1.x + c2 * a2.x) * un;
    f.y += (a0.y + c1 * a1.y + c2 * a2.y) * un;
    f.z += (b0.x + c1 * b1.x + c2 * b2.x) * un;
    f.w += (b0.y + c1 * b1.y + c2 * b2.y) * un;

    *(float4*)(out + (size_t)r * Dx + lane * 4) = f;
}

extern "C" void kernel_launch(void* const* d_in, const int* in_sizes, int n_in,
                              void* d_out, int out_size) {
    const float* uf  = (const float*)d_in[0];
    const float* itf = (const float*)d_in[1];
    const int*   eu  = (const int*)d_in[2];
    const int*   ei  = (const int*)d_in[3];
    const int*   usr = (const int*)d_in[4];
    const int*   pos = (const int*)d_in[5];
    const int*   neg = (const int*)d_in[6];
    float* out = (float*)d_out;

    void *p_uf16, *p_if16, *p_hu[3], *p_hi[3];
    cudaGetSymbolAddress(&p_uf16, g_uf16);
    cudaGetSymbolAddress(&p_if16, g_if16);
    {
        void* tmp;
        cudaGetSymbolAddress(&tmp, g_hu16);
        for (int k = 0; k < 3; ++k) p_hu[k] = (char*)tmp + (size_t)k * NUx * 32 * sizeof(__half2);
        cudaGetSymbolAddress(&tmp, g_hi16);
        for (int k = 0; k < 3; ++k) p_hi[k] = (char*)tmp + (size_t)k * NIx * 32 * sizeof(__half2);
    }

    // ---- CSR build + pre-scaled fp16 staging (4 launches before agg) ----
    // g_deg is zero at entry (static init on run 1; k_out re-zeroes it)
    k_deg<<<DEGB, 256>>>(eu, ei);                                    // #1
    k_scan_blocks2<<<SCANB_U + SCANB_I, SB>>>();                     // #2
    k_scan_add2<<<SCANB_U + SCANB_I, SB>>>();                        // #3
    k_cvtfill<<<FILLB + CVTB, 256>>>(uf, itf, eu, ei);               // #4

    const unsigned npairs = (NUx + NIx) / 2;
    const unsigned gagg = (unsigned)(((size_t)npairs * 32 + 255) / 256);

    // ---- 3 propagation layers ----
    k_agg<<<gagg, 256>>>((const __half2*)p_uf16, (const __half2*)p_if16,
                         (__half2*)p_hu[0], (__half2*)p_hi[0]);
    k_agg<<<gagg, 256>>>((const __half2*)p_hu[0], (const __half2*)p_hi[0],
                         (__half2*)p_hu[1], (__half2*)p_hi[1]);
    k_agg<<<gagg, 256>>>((const __half2*)p_hu[1], (const __half2*)p_hi[1],
                         (__half2*)p_hu[2], (__half2*)p_hi[2]);

    // ---- output gather (unscale h', compute e on the fly) ----
    k_out<<<(3 * Bx * 16 + 255) / 256, 256>>>(uf, itf, usr, pos, neg, out);
}